// round 12
// baseline (speedup 1.0000x reference)
#include <cuda_runtime.h>
#include <cuda_fp16.h>
#include <mma.h>
#include <cstdint>

using namespace nvcuda;

// GCN 2-layer, CSR two-phase aggregation, sm_100a.
// GEMM on tensor cores (wmma fp16 in / fp32 accum), H stored fp16,
// agg layer-1 emits fp16 directly for GEMM-2's A operand.

#define N_NODES 100000
#define N_EDGES 1600000
#define D 64
#define FIXS 33554432.0f          // 2^25 fixed-point scale for weight sums
#define FIXR (1.0f / 33554432.0f)

__device__ unsigned long long g_pk[N_NODES];  // (cnt << 32) | fixed_weight_sum
__device__ float g_dis[N_NODES];        // rsqrt(degree)
__device__ int   g_cnt[N_NODES];        // in-degree (edges only)
__device__ int   g_row[N_NODES];        // CSR row start (bump-allocated)
__device__ int   g_total;               // bump allocator
__device__ int   g_pos[N_EDGES];        // within-bin slot (from hist atomic)
__device__ int2  g_bins[N_EDGES];       // (src, w-as-int), dst-binned
__device__ uint2 g_h[N_NODES * 16];     // Hs fp16 (gemm out / agg in)
__device__ uint2 g_hh[N_NODES * 16];    // agg1 out fp16 (gemm2 in)

// ---------------------------------------------------------------------------
__global__ void k_init() {
    int i = blockIdx.x * blockDim.x + threadIdx.x;
    if (i < N_NODES) g_pk[i] = 0ULL;
    if (i == 0) g_total = 0;
}

// one packed 64-bit atomic per edge: count (hi) + fixed-point weight sum (lo)
__global__ void k_hist(const int* __restrict__ dst,
                       const float* __restrict__ w) {
    int t = blockIdx.x * blockDim.x + threadIdx.x;
    if (t >= N_EDGES / 4) return;
    int4   dv = ((const int4*)dst)[t];
    float4 wv = ((const float4*)w)[t];
    unsigned long long a0 = (1ULL << 32) | (unsigned)__float2uint_rn(wv.x * FIXS);
    unsigned long long a1 = (1ULL << 32) | (unsigned)__float2uint_rn(wv.y * FIXS);
    unsigned long long a2 = (1ULL << 32) | (unsigned)__float2uint_rn(wv.z * FIXS);
    unsigned long long a3 = (1ULL << 32) | (unsigned)__float2uint_rn(wv.w * FIXS);
    int p0 = (int)(atomicAdd(&g_pk[dv.x], a0) >> 32);
    int p1 = (int)(atomicAdd(&g_pk[dv.y], a1) >> 32);
    int p2 = (int)(atomicAdd(&g_pk[dv.z], a2) >> 32);
    int p3 = (int)(atomicAdd(&g_pk[dv.w], a3) >> 32);
    ((int4*)g_pos)[t] = make_int4(p0, p1, p2, p3);
}

__global__ void k_alloc() {
    int i = blockIdx.x * blockDim.x + threadIdx.x;
    if (i >= N_NODES) return;
    unsigned long long pk = g_pk[i];
    int cnt = (int)(pk >> 32);
    float deg = 1.0f + (float)(unsigned)(pk & 0xFFFFFFFFULL) * FIXR;
    g_dis[i] = rsqrtf(deg);
    g_cnt[i] = cnt;
    g_row[i] = atomicAdd(&g_total, cnt);
}

// fill bins: payload (src, raw w); one row[dst] gather
__global__ void k_fill(const int* __restrict__ src,
                       const int* __restrict__ dst,
                       const float* __restrict__ w) {
    int t = blockIdx.x * blockDim.x + threadIdx.x;
    if (t >= N_EDGES / 4) return;
    int4   sv = ((const int4*)src)[t];
    int4   dv = ((const int4*)dst)[t];
    int4   pv = ((const int4*)g_pos)[t];
    float4 wv = ((const float4*)w)[t];
    int r0 = g_row[dv.x], r1 = g_row[dv.y], r2 = g_row[dv.z], r3 = g_row[dv.w];
    g_bins[r0 + pv.x] = make_int2(sv.x, __float_as_int(wv.x));
    g_bins[r1 + pv.y] = make_int2(sv.y, __float_as_int(wv.y));
    g_bins[r2 + pv.z] = make_int2(sv.z, __float_as_int(wv.z));
    g_bins[r3 + pv.w] = make_int2(sv.w, __float_as_int(wv.w));
}

// ---------------------------------------------------------------------------
// tensor-core GEMM: Hs[row] = half( dis[row] * (X[row] @ W) )
// block = 64 rows, 4 warps; wmma m16n16k16, fp16 in / fp32 accum.
// IN16: input already fp16 row-major 64/node (agg1 output); else fp32.
// ---------------------------------------------------------------------------
template <int IN16>
__global__ void __launch_bounds__(128) k_gemm_mma(const void* __restrict__ Xin,
                                                  const float* __restrict__ W,
                                                  uint2* __restrict__ H) {
    __shared__ __half Wh[D * D];      // 8KB
    __shared__ __half Xh[64 * D];     // 8KB
    __shared__ float  Cs[64 * D];     // 16KB
    int tid = threadIdx.x;
    int rowbase = blockIdx.x * 64;

    // stage W as fp16 (1024 float4 -> 1024 uint2)
    {
        const float4* W4 = (const float4*)W;
#pragma unroll
        for (int i = tid; i < 1024; i += 128) {
            float4 v = W4[i];
            __half2 h0 = __floats2half2_rn(v.x, v.y);
            __half2 h1 = __floats2half2_rn(v.z, v.w);
            ((uint2*)Wh)[i] = make_uint2(*(unsigned*)&h0, *(unsigned*)&h1);
        }
    }
    // stage X tile as fp16 (guarded tail)
    if (IN16) {
        const uint4* X16 = (const uint4*)Xin;   // 8 uint4 per node
        for (int i = tid; i < 512; i += 128) {
            int row = rowbase + (i >> 3);
            ((uint4*)Xh)[i] = (row < N_NODES) ? X16[(size_t)row * 8 + (i & 7)]
                                              : make_uint4(0, 0, 0, 0);
        }
    } else {
        const float4* Xf = (const float4*)Xin;  // 16 float4 per node
        for (int i = tid; i < 1024; i += 128) {
            int row = rowbase + (i >> 4);
            float4 v = (row < N_NODES) ? Xf[(size_t)row * 16 + (i & 15)]
                                       : make_float4(0, 0, 0, 0);
            __half2 h0 = __floats2half2_rn(v.x, v.y);
            __half2 h1 = __floats2half2_rn(v.z, v.w);
            ((uint2*)Xh)[i] = make_uint2(*(unsigned*)&h0, *(unsigned*)&h1);
        }
    }
    __syncthreads();

    int wid = tid >> 5;
    wmma::fragment<wmma::accumulator, 16, 16, 16, float> c[4];
#pragma unroll
    for (int n = 0; n < 4; ++n) wmma::fill_fragment(c[n], 0.0f);

#pragma unroll
    for (int k = 0; k < 4; ++k) {
        wmma::fragment<wmma::matrix_a, 16, 16, 16, __half, wmma::row_major> a;
        wmma::load_matrix_sync(a, Xh + (wid * 16) * D + k * 16, D);
#pragma unroll
        for (int n = 0; n < 4; ++n) {
            wmma::fragment<wmma::matrix_b, 16, 16, 16, __half, wmma::row_major> b;
            wmma::load_matrix_sync(b, Wh + (k * 16) * D + n * 16, D);
            wmma::mma_sync(c[n], a, b, c[n]);
        }
    }
#pragma unroll
    for (int n = 0; n < 4; ++n)
        wmma::store_matrix_sync(Cs + (wid * 16) * D + n * 16, c[n], D,
                                wmma::mem_row_major);
    __syncthreads();

    // epilogue: scale by dis[row], pack fp16, store (1024 uint2 per block)
    for (int i = tid; i < 1024; i += 128) {
        int r = i >> 4;                  // local row
        int j = i & 15;                  // uint2 index (4 channels)
        int row = rowbase + r;
        if (row >= N_NODES) break;
        float di = g_dis[row];
        const float* cp = Cs + r * D + j * 4;
        __half2 h0 = __floats2half2_rn(cp[0] * di, cp[1] * di);
        __half2 h1 = __floats2half2_rn(cp[2] * di, cp[3] * di);
        H[(size_t)row * 16 + j] = make_uint2(*(unsigned*)&h0, *(unsigned*)&h1);
    }
}

// ---------------------------------------------------------------------------
// CSR aggregate: 16 lanes per node; lane owns 4 channels (uint2 = 2 half2).
// fp32 accumulation; fused self-loop, dis scale, ReLU. x8 unroll (MLP=8).
// OUT16: emit fp16 (feeds gemm2); else fp32 (final output).
// ---------------------------------------------------------------------------
__device__ __forceinline__ void acc_h4(float4& acc, uint2 v, float nm) {
    float2 f0 = __half22float2(*(__half2*)&v.x);
    float2 f1 = __half22float2(*(__half2*)&v.y);
    acc.x = fmaf(nm, f0.x, acc.x); acc.y = fmaf(nm, f0.y, acc.y);
    acc.z = fmaf(nm, f1.x, acc.z); acc.w = fmaf(nm, f1.y, acc.w);
}

template <int OUT16>
__global__ void __launch_bounds__(256) k_agg(const uint2* __restrict__ H,
                                             void* __restrict__ A) {
    int idx = blockIdx.x * 256 + threadIdx.x;
    int n = idx >> 4;
    if (n >= N_NODES) return;
    int l = idx & 15;

    int e   = g_row[n];
    int end = e + g_cnt[n];

    float4 acc;
    {   // self-loop term Hs[n]
        uint2 sv = H[(size_t)n * 16 + l];
        float2 f0 = __half22float2(*(__half2*)&sv.x);
        float2 f1 = __half22float2(*(__half2*)&sv.y);
        acc = make_float4(f0.x, f0.y, f1.x, f1.y);
    }

    for (; e + 8 <= end; e += 8) {
        int2 p[8];
#pragma unroll
        for (int j = 0; j < 8; ++j) p[j] = g_bins[e + j];
        uint2 v[8];
#pragma unroll
        for (int j = 0; j < 8; ++j) v[j] = H[(size_t)p[j].x * 16 + l];
#pragma unroll
        for (int j = 0; j < 8; ++j) acc_h4(acc, v[j], __int_as_float(p[j].y));
    }
    if (e + 4 <= end) {
        int2 p[4];
#pragma unroll
        for (int j = 0; j < 4; ++j) p[j] = g_bins[e + j];
        uint2 v[4];
#pragma unroll
        for (int j = 0; j < 4; ++j) v[j] = H[(size_t)p[j].x * 16 + l];
#pragma unroll
        for (int j = 0; j < 4; ++j) acc_h4(acc, v[j], __int_as_float(p[j].y));
        e += 4;
    }
    for (; e < end; ++e) {
        int2 p = g_bins[e];
        uint2 v = H[(size_t)p.x * 16 + l];
        acc_h4(acc, v, __int_as_float(p.y));
    }

    float di = g_dis[n];
    acc.x = fmaxf(acc.x * di, 0.f); acc.y = fmaxf(acc.y * di, 0.f);
    acc.z = fmaxf(acc.z * di, 0.f); acc.w = fmaxf(acc.w * di, 0.f);
    if (OUT16) {
        __half2 h0 = __floats2half2_rn(acc.x, acc.y);
        __half2 h1 = __floats2half2_rn(acc.z, acc.w);
        ((uint2*)A)[(size_t)n * 16 + l] =
            make_uint2(*(unsigned*)&h0, *(unsigned*)&h1);
    } else {
        ((float4*)A)[(size_t)n * 16 + l] = acc;
    }
}

// ---------------------------------------------------------------------------
extern "C" void kernel_launch(void* const* d_in, const int* in_sizes, int n_in,
                              void* d_out, int out_size) {
    const float* x   = (const float*)d_in[0];
    const int*   ei  = (const int*)d_in[1];     // int32 (JAX x64 disabled)
    const float* w   = (const float*)d_in[2];
    const float* W0  = (const float*)d_in[3];
    const float* W1  = (const float*)d_in[4];
    float* out = (float*)d_out;

    const int* src = ei;
    const int* dst = ei + N_EDGES;

    uint2 *p_h, *p_hh;
    cudaGetSymbolAddress((void**)&p_h, g_h);
    cudaGetSymbolAddress((void**)&p_hh, g_hh);

    const int TB = 256;
    int gN    = (N_NODES + TB - 1) / TB;
    int gE4   = (N_EDGES / 4 + TB - 1) / TB;
    int gAgg  = (N_NODES * 16 + TB - 1) / TB;
    int gGemm = (N_NODES + 63) / 64;

    // prep
    k_init<<<gN, TB>>>();
    k_hist<<<gE4, TB>>>(dst, w);
    k_alloc<<<gN, TB>>>();
    k_fill<<<gE4, TB>>>(src, dst, w);

    // layer 1: fp32 in, fp16 H; agg emits fp16 for gemm2
    k_gemm_mma<0><<<gGemm, 128>>>(x, W0, p_h);
    k_agg<1><<<gAgg, TB>>>(p_h, p_hh);

    // layer 2: fp16 in, fp16 H; agg emits fp32 final output
    k_gemm_mma<1><<<gGemm, 128>>>(p_hh, W1, p_h);
    k_agg<0><<<gAgg, TB>>>(p_h, out);
}